// round 2
// baseline (speedup 1.0000x reference)
#include <cuda_runtime.h>
#include <cuda_bf16.h>
#include <cstddef>

// Problem constants
constexpr int Bc = 32, Lc = 256, Dc = 256, Hc = 256, Ec = 8, NLc = 4, KCONV = 4;
constexpr int BE  = Bc * Ec;                       // 256 independent sequences
constexpr long long MT   = (long long)BE * Lc;     // 65536 GEMM rows per layer
constexpr long long BELH = (long long)BE * Lc * Hc;// 16777216 output h elements

// Scratch (device globals: allocation-free per harness rules)
__device__ float g_ln [Bc * Lc * Dc];      // 8 MB
__device__ float g_u  [Bc * Lc * Dc];      // 8 MB
__device__ float g_pre[BE * Lc * Hc];      // 64 MB
__device__ float g_y  [BE * Lc * Hc];      // 64 MB

typedef unsigned long long u64;

__device__ __forceinline__ u64 ffma2(u64 a, u64 b, u64 c)
{
    u64 d;
    asm("fma.rn.f32x2 %0, %1, %2, %3;" : "=l"(d) : "l"(a), "l"(b), "l"(c));
    return d;
}
__device__ __forceinline__ u64 fadd2(u64 a, u64 b)
{
    u64 d;
    asm("add.rn.f32x2 %0, %1, %2;" : "=l"(d) : "l"(a), "l"(b));
    return d;
}
__device__ __forceinline__ u64 dup2(float x)
{
    u64 d;
    asm("mov.b64 %0, {%1, %1};" : "=l"(d) : "f"(x));
    return d;
}
__device__ __forceinline__ float lo32(u64 v){ return __uint_as_float((unsigned)v); }
__device__ __forceinline__ float hi32(u64 v){ return __uint_as_float((unsigned)(v >> 32)); }
__device__ __forceinline__ float tanh_fast(float x)
{
    float r;
    asm("tanh.approx.f32 %0, %1;" : "=f"(r) : "f"(x));
    return r;
}

// ---------------------------------------------------------------------------
// Kernel 1: LayerNorm over D
// ---------------------------------------------------------------------------
__global__ void ln_kernel(const float* __restrict__ x,
                          const float* __restrict__ g,
                          const float* __restrict__ bt,
                          float* __restrict__ out)
{
    __shared__ float red[16];
    int m = blockIdx.x;          // b*L + l
    int d = threadIdx.x;         // 0..255
    float v = x[(size_t)m * Dc + d];
    float s1 = v, s2 = v * v;
    #pragma unroll
    for (int off = 16; off; off >>= 1) {
        s1 += __shfl_xor_sync(0xffffffffu, s1, off);
        s2 += __shfl_xor_sync(0xffffffffu, s2, off);
    }
    int w = d >> 5, lane = d & 31;
    if (lane == 0) { red[w] = s1; red[8 + w] = s2; }
    __syncthreads();
    float S1 = 0.f, S2 = 0.f;
    #pragma unroll
    for (int i = 0; i < 8; i++) { S1 += red[i]; S2 += red[8 + i]; }
    float mean = S1 * (1.0f / Dc);
    float var  = fmaxf(S2 * (1.0f / Dc) - mean * mean, 0.0f);
    out[(size_t)m * Dc + d] = (v - mean) * rsqrtf(var + 1e-5f) * g[d] + bt[d];
}

// ---------------------------------------------------------------------------
// Kernel 2: depthwise causal conv1d (K=4, left pad 3) + bias
// ---------------------------------------------------------------------------
__global__ void conv_kernel(const float* __restrict__ ln,
                            const float* __restrict__ cw,
                            const float* __restrict__ cb,
                            float* __restrict__ u)
{
    int m = blockIdx.x;          // b*L + l
    int d = threadIdx.x;
    int b = m / Lc, l = m % Lc;
    float acc = cb[d];
    #pragma unroll
    for (int k = 0; k < KCONV; k++) {
        int ls = l - (KCONV - 1) + k;
        if (ls >= 0)
            acc += cw[d * KCONV + k] * ln[((size_t)b * Lc + ls) * Dc + d];
    }
    u[(size_t)m * Dc + d] = acc;
}

// ---------------------------------------------------------------------------
// Kernel 3: input projection GEMM (packed f32x2 FMAs)
//   pre[m,h] = s[e,h] * ( sum_d X[m,d]*r[e,d]*W[h,d] ) + bvec[h]
// ---------------------------------------------------------------------------
#define GBM 64
#define GBN 64
#define GBK 16
__global__ void __launch_bounds__(256)
gemm_pre_kernel(const float* __restrict__ X, int bcast,
                const float* __restrict__ W,
                const float* __restrict__ r_l,
                const float* __restrict__ s_l,
                const float* __restrict__ b_l,
                float* __restrict__ pre)
{
    __shared__ __align__(16) float As[GBK][GBM];
    __shared__ __align__(16) float Bs[GBK][GBN];

    int m0 = blockIdx.x * GBM;
    int h0 = blockIdx.y * GBN;
    int tid = threadIdx.x;
    int tx = tid & 15, ty = tid >> 4;

    int e_blk = (m0 / Lc) % Ec;
    int b_blk = m0 / (Ec * Lc);
    int l0    = m0 % Lc;

    int lr = tid >> 2, seg = tid & 3;
    const float* xrow = bcast ? (X + ((size_t)b_blk * Lc + (l0 + lr)) * Dc)
                              : (X + (size_t)(m0 + lr) * Dc);
    const float* rrow = r_l + e_blk * Dc;
    const float* wrow = W + (size_t)(h0 + lr) * Dc;

    u64 acc2[2][4];   // [i-pair][j]; lo = row ty*4+2p, hi = row ty*4+2p+1
    #pragma unroll
    for (int p = 0; p < 2; p++)
        #pragma unroll
        for (int j = 0; j < 4; j++) acc2[p][j] = 0ull;

    for (int d0 = 0; d0 < Dc; d0 += GBK) {
        float4 a4 = *(const float4*)(xrow + d0 + seg * 4);
        float4 r4 = *(const float4*)(rrow + d0 + seg * 4);
        float4 b4 = *(const float4*)(wrow + d0 + seg * 4);
        As[seg * 4 + 0][lr] = a4.x * r4.x;
        As[seg * 4 + 1][lr] = a4.y * r4.y;
        As[seg * 4 + 2][lr] = a4.z * r4.z;
        As[seg * 4 + 3][lr] = a4.w * r4.w;
        Bs[seg * 4 + 0][lr] = b4.x;
        Bs[seg * 4 + 1][lr] = b4.y;
        Bs[seg * 4 + 2][lr] = b4.z;
        Bs[seg * 4 + 3][lr] = b4.w;
        __syncthreads();
        #pragma unroll
        for (int kk = 0; kk < GBK; kk++) {
            ulonglong2 ap = *(const ulonglong2*)&As[kk][ty * 4];
            float4 bv = *(const float4*)&Bs[kk][tx * 4];
            u64 bd0 = dup2(bv.x), bd1 = dup2(bv.y), bd2 = dup2(bv.z), bd3 = dup2(bv.w);
            acc2[0][0] = ffma2(ap.x, bd0, acc2[0][0]);
            acc2[0][1] = ffma2(ap.x, bd1, acc2[0][1]);
            acc2[0][2] = ffma2(ap.x, bd2, acc2[0][2]);
            acc2[0][3] = ffma2(ap.x, bd3, acc2[0][3]);
            acc2[1][0] = ffma2(ap.y, bd0, acc2[1][0]);
            acc2[1][1] = ffma2(ap.y, bd1, acc2[1][1]);
            acc2[1][2] = ffma2(ap.y, bd2, acc2[1][2]);
            acc2[1][3] = ffma2(ap.y, bd3, acc2[1][3]);
        }
        __syncthreads();
    }

    float4 s4 = *(const float4*)(s_l + (size_t)e_blk * Hc + h0 + tx * 4);
    float4 bi = *(const float4*)(b_l + h0 + tx * 4);
    float sv[4] = {s4.x, s4.y, s4.z, s4.w};
    float bv2[4] = {bi.x, bi.y, bi.z, bi.w};
    #pragma unroll
    for (int p = 0; p < 2; p++) {
        #pragma unroll
        for (int hh = 0; hh < 2; hh++) {
            int i = 2 * p + hh;
            float* orow = pre + (size_t)(m0 + ty * 4 + i) * Hc + h0 + tx * 4;
            float4 o;
            float a0 = hh ? hi32(acc2[p][0]) : lo32(acc2[p][0]);
            float a1 = hh ? hi32(acc2[p][1]) : lo32(acc2[p][1]);
            float a2 = hh ? hi32(acc2[p][2]) : lo32(acc2[p][2]);
            float a3 = hh ? hi32(acc2[p][3]) : lo32(acc2[p][3]);
            o.x = a0 * sv[0] + bv2[0];
            o.y = a1 * sv[1] + bv2[1];
            o.z = a2 * sv[2] + bv2[2];
            o.w = a3 * sv[3] + bv2[3];
            *(float4*)orow = o;
        }
    }
}

// ---------------------------------------------------------------------------
// Kernel 4: persistent per-row recurrence, (k-group x j-group) split.
//   Block = 2 rows, 256 threads. Thread (kg=t>>3, jg=t&7) computes partials
//   for 8 output channels (k = kg*8..kg*8+7) over j in [jg*32, jg*32+32).
//   Weights: k-offsets 0..4 in registers (80 u64), 5..7 in smem (24 u64).
//   3-stage xor-shuffle reduce leaves channel k = t on thread t.
// ---------------------------------------------------------------------------
#define RNN_W_SMEM_ENT (24 * 256)                       // ulonglong2 entries
#define RNN2_SMEM ((RNN_W_SMEM_ENT) * 16 + 2 * 2 * 256 * 4)

__global__ void __launch_bounds__(256, 1)
rnn_kernel(const float* __restrict__ pre,
           const float* __restrict__ Whh,
           float* __restrict__ y,
           float* __restrict__ hlast)
{
    extern __shared__ __align__(16) char smraw[];
    ulonglong2* wsm = (ulonglong2*)smraw;                       // [24][256]
    float* hbuf = (float*)(smraw + (size_t)RNN_W_SMEM_ENT * 16);// [2][2][256]

    int t  = threadIdx.x;
    int jg = t & 7;          // j-group: j in [jg*32, jg*32+32)
    int kg = t >> 3;         // k-group: k in [kg*8, kg*8+8)
    int row0 = blockIdx.x * 2;
    int row1 = row0 + 1;

    // ---- weight load: per-thread 128 u64 pairs; 80 in regs, 48 via smem ----
    const u64* wg = (const u64*)Whh;   // Whh[k][j] -> u64 idx k*128 + j/2
    u64 wr[80];
    #pragma unroll
    for (int kidx = 0; kidx < 5; kidx++)
        #pragma unroll
        for (int m = 0; m < 16; m++)
            wr[kidx * 16 + m] = wg[(size_t)(kg * 8 + kidx) * 128 + jg * 16 + m];
    #pragma unroll
    for (int kidx = 5; kidx < 8; kidx++)
        #pragma unroll
        for (int q = 0; q < 8; q++) {
            int e = (kidx - 5) * 8 + q;
            ulonglong2 wv;
            wv.x = wg[(size_t)(kg * 8 + kidx) * 128 + jg * 16 + 2 * q];
            wv.y = wg[(size_t)(kg * 8 + kidx) * 128 + jg * 16 + 2 * q + 1];
            wsm[e * 256 + t] = wv;
        }

    hbuf[0 * 512 + 0 * 256 + t] = 0.f;
    hbuf[0 * 512 + 1 * 256 + t] = 0.f;
    __syncthreads();

    const float* pre0 = pre + (size_t)row0 * Lc * Hc + t;
    const float* pre1 = pre + (size_t)row1 * Lc * Hc + t;
    float* y0 = y + (size_t)row0 * Lc * Hc + t;
    float* y1 = y + (size_t)row1 * Lc * Hc + t;
    const ulonglong2* wsmt = wsm + t;

    bool s4 = (jg & 4) != 0, s2 = (jg & 2) != 0, s1 = (jg & 1) != 0;
    unsigned FULL = 0xffffffffu;

    int p = 0;
    float cur0 = 0.f, cur1 = 0.f;
    #pragma unroll 1
    for (int tstep = 0; tstep < Lc; tstep++) {
        float pv0 = pre0[(size_t)tstep * Hc];
        float pv1 = pre1[(size_t)tstep * Hc];

        const ulonglong2* h0v = (const ulonglong2*)(hbuf + p * 512 + jg * 32);
        const ulonglong2* h1v = (const ulonglong2*)(hbuf + p * 512 + 256 + jg * 32);

        u64 a0[8], a1[8];
        #pragma unroll
        for (int i = 0; i < 8; i++) { a0[i] = 0ull; a1[i] = 0ull; }

        #pragma unroll
        for (int q = 0; q < 8; q++) {
            ulonglong2 hv0 = h0v[q];
            ulonglong2 hv1 = h1v[q];
            #pragma unroll
            for (int kidx = 0; kidx < 5; kidx++) {
                u64 w0 = wr[kidx * 16 + 2 * q];
                u64 w1 = wr[kidx * 16 + 2 * q + 1];
                a0[kidx] = ffma2(w0, hv0.x, a0[kidx]);
                a0[kidx] = ffma2(w1, hv0.y, a0[kidx]);
                a1[kidx] = ffma2(w0, hv1.x, a1[kidx]);
                a1[kidx] = ffma2(w1, hv1.y, a1[kidx]);
            }
            #pragma unroll
            for (int kidx = 5; kidx < 8; kidx++) {
                ulonglong2 wv = wsmt[((kidx - 5) * 8 + q) * 256];
                a0[kidx] = ffma2(wv.x, hv0.x, a0[kidx]);
                a0[kidx] = ffma2(wv.y, hv0.y, a0[kidx]);
                a1[kidx] = ffma2(wv.x, hv1.x, a1[kidx]);
                a1[kidx] = ffma2(wv.y, hv1.y, a1[kidx]);
            }
        }

        // ---- 3-stage shuffle reduce; thread t ends up with channel k = t ----
        float red0, red1;
        {
            // stage b=4
            u64 k0 = s4 ? a0[4] : a0[0], x0 = s4 ? a0[0] : a0[4];
            u64 k1 = s4 ? a0[5] : a0[1], x1 = s4 ? a0[1] : a0[5];
            u64 k2 = s4 ? a0[6] : a0[2], x2 = s4 ? a0[2] : a0[6];
            u64 k3 = s4 ? a0[7] : a0[3], x3 = s4 ? a0[3] : a0[7];
            k0 = fadd2(k0, __shfl_xor_sync(FULL, x0, 4));
            k1 = fadd2(k1, __shfl_xor_sync(FULL, x1, 4));
            k2 = fadd2(k2, __shfl_xor_sync(FULL, x2, 4));
            k3 = fadd2(k3, __shfl_xor_sync(FULL, x3, 4));
            // stage b=2
            u64 m0 = s2 ? k2 : k0, z0 = s2 ? k0 : k2;
            u64 m1 = s2 ? k3 : k1, z1 = s2 ? k1 : k3;
            m0 = fadd2(m0, __shfl_xor_sync(FULL, z0, 2));
            m1 = fadd2(m1, __shfl_xor_sync(FULL, z1, 2));
            // stage b=1
            u64 f = s1 ? m1 : m0, z = s1 ? m0 : m1;
            f = fadd2(f, __shfl_xor_sync(FULL, z, 1));
            red0 = lo32(f) + hi32(f);
        }
        {
            u64 k0 = s4 ? a1[4] : a1[0], x0 = s4 ? a1[0] : a1[4];
            u64 k1 = s4 ? a1[5] : a1[1], x1 = s4 ? a1[1] : a1[5];
            u64 k2 = s4 ? a1[6] : a1[2], x2 = s4 ? a1[2] : a1[6];
            u64 k3 = s4 ? a1[7] : a1[3], x3 = s4 ? a1[3] : a1[7];
            k0 = fadd2(k0, __shfl_xor_sync(FULL, x0, 4));
            k1 = fadd2(k1, __shfl_xor_sync(FULL, x1, 4));
            k2 = fadd2(k2, __shfl_xor_sync(FULL, x2, 4));
            k3 = fadd2(k3, __shfl_xor_sync(FULL, x3, 4));
            u64 m0 = s2 ? k2 : k0, z0 = s2 ? k0 : k2;
            u64 m1 = s2 ? k3 : k1, z1 = s2 ? k1 : k3;
            m0 = fadd2(m0, __shfl_xor_sync(FULL, z0, 2));
            m1 = fadd2(m1, __shfl_xor_sync(FULL, z1, 2));
            u64 f = s1 ? m1 : m0, z = s1 ? m0 : m1;
            f = fadd2(f, __shfl_xor_sync(FULL, z, 1));
            red1 = lo32(f) + hi32(f);
        }

        cur0 = tanh_fast(pv0 + red0);
        cur1 = tanh_fast(pv1 + red1);
        y0[(size_t)tstep * Hc] = cur0;
        y1[(size_t)tstep * Hc] = cur1;
        int np = p ^ 1;
        hbuf[np * 512 + t]       = cur0;
        hbuf[np * 512 + 256 + t] = cur1;
        __syncthreads();
        p = np;
    }
    if (hlast) {
        hlast[(size_t)row0 * Hc + t] = cur0;
        hlast[(size_t)row1 * Hc + t] = cur1;
    }
}

// ---------------------------------------------------------------------------
// Launch
// ---------------------------------------------------------------------------
extern "C" void kernel_launch(void* const* d_in, const int* in_sizes, int n_in,
                              void* d_out, int out_size)
{
    const float* x      = (const float*)d_in[0];
    const float* conv_w = (const float*)d_in[1];
    const float* conv_b = (const float*)d_in[2];
    const float* ln_g   = (const float*)d_in[3];
    const float* ln_b   = (const float*)d_in[4];
    const float* W_ih   = (const float*)d_in[5];
    const float* W_hh   = (const float*)d_in[6];
    const float* r_in   = (const float*)d_in[7];
    const float* s_in   = (const float*)d_in[8];
    const float* b_in   = (const float*)d_in[9];

    float *p_ln, *p_u, *p_pre, *p_y;
    cudaGetSymbolAddress((void**)&p_ln,  g_ln);
    cudaGetSymbolAddress((void**)&p_u,   g_u);
    cudaGetSymbolAddress((void**)&p_pre, g_pre);
    cudaGetSymbolAddress((void**)&p_y,   g_y);

    cudaFuncSetAttribute(rnn_kernel,
                         cudaFuncAttributeMaxDynamicSharedMemorySize,
                         RNN2_SMEM);

    float* out = (float*)d_out;
    float* y_final;
    float* hlast;
    long long need = BELH + (long long)BE * Hc;
    if ((long long)out_size >= need)       { y_final = out;  hlast = out + BELH; }
    else if ((long long)out_size >= BELH)  { y_final = out;  hlast = nullptr; }
    else                                   { y_final = p_y;  hlast = out; }

    ln_kernel  <<<Bc * Lc, 256>>>(x, ln_g, ln_b, p_ln);
    conv_kernel<<<Bc * Lc, 256>>>(p_ln, conv_w, conv_b, p_u);

    dim3 ggrid((unsigned)(MT / GBM), Hc / GBN);
    for (int i = 0; i < NLc; i++) {
        const float* Xin = (i == 0) ? p_u : p_y;
        int bcast = (i == 0) ? 1 : 0;
        gemm_pre_kernel<<<ggrid, 256>>>(Xin, bcast,
                                        W_ih + (size_t)i * Hc * Dc,
                                        r_in + (size_t)i * Ec * Dc,
                                        s_in + (size_t)i * Ec * Hc,
                                        b_in + (size_t)i * Hc,
                                        p_pre);
        float* yout = (i == NLc - 1) ? y_final : p_y;
        float* hl   = (i == NLc - 1) ? hlast   : nullptr;
        rnn_kernel<<<BE / 2, 256, RNN2_SMEM>>>(p_pre,
                                               W_hh + (size_t)i * Hc * Hc,
                                               yout, hl);
    }
}